// round 1
// baseline (speedup 1.0000x reference)
#include <cuda_runtime.h>
#include <cstdint>

// VQ: for each of N=131072 pixel vectors (D=64) find nearest of K=512 codes,
// emit gathered code vectors (NHWC) followed by indices (as float).
// argmin ||x-e||^2 == argmax (x.e - 0.5*||e||^2)

#define D  64
#define K  512
#define MT 128    // pixels per CTA
#define T  256    // threads per CTA

__device__ float g_et[D * K];   // transposed codebook e_t[d][k]
__device__ float g_hes[K];      // 0.5*||e_k||^2

// ---------------------------------------------------------------------------
// Prep: transpose codebook + half squared norms. Runs every launch (graph-safe).
// ---------------------------------------------------------------------------
__global__ void vq_prep(const float* __restrict__ embed) {
    int k = blockIdx.x;
    int d = threadIdx.x;
    float v = embed[k * D + d];
    g_et[d * K + k] = v;
    float s = v * v;
    #pragma unroll
    for (int o = 16; o > 0; o >>= 1) s += __shfl_down_sync(0xffffffffu, s, o);
    __shared__ float ws[2];
    if ((d & 31) == 0) ws[d >> 5] = s;
    __syncthreads();
    if (d == 0) g_hes[k] = 0.5f * (ws[0] + ws[1]);
}

// ---------------------------------------------------------------------------
// Main: per CTA, 128 pixels x 512 codes, D=64 reduction via packed f32x2 FMA.
// SMEM: codebook 128KB + x-tile 32KB + norms 2KB + best 1KB = 167KB (1 CTA/SM)
// ---------------------------------------------------------------------------
__global__ void __launch_bounds__(T, 1) vq_main(const float* __restrict__ x,
                                                const float* __restrict__ embed,
                                                float* __restrict__ outq,
                                                float* __restrict__ outi) {
    extern __shared__ float smem[];
    float* se   = smem;            // [D][K]
    float* sx   = se + D * K;      // [D][MT]
    float* shes = sx + D * MT;     // [K]
    unsigned long long* sbest = (unsigned long long*)(shes + K);  // [MT]

    const int tid = threadIdx.x;
    const int n0  = blockIdx.x * MT;     // global pixel base (= b*4096 + hw0)
    const int b   = n0 >> 12;            // HW = 4096, MT divides it
    const int hw0 = n0 & 4095;

    // Load transposed codebook (straight float4 copy, fully coalesced)
    {
        const float4* g4 = (const float4*)g_et;
        float4* s4 = (float4*)se;
        #pragma unroll 8
        for (int i = tid; i < D * K / 4; i += T) s4[i] = g4[i];
    }
    // Load x tile transposed: sx[c][j] = x[b][c][hw0+j], coalesced per channel
    for (int i = tid; i < D * (MT / 4); i += T) {
        int c = i >> 5, j4 = i & 31;
        float4 v = *(const float4*)(x + (((size_t)(b * D + c)) << 12) + hw0 + (j4 << 2));
        *(float4*)(sx + c * MT + (j4 << 2)) = v;
    }
    for (int i = tid; i < K;  i += T) shes[i]  = g_hes[i];
    for (int i = tid; i < MT; i += T) sbest[i] = 0ull;
    __syncthreads();

    // 16 m-groups (8 pixels each) x 16 k-groups (32 codes each, in 2 chunks of 16)
    const int mg = tid & 15;   // -> strided x reads within warp
    const int kg = tid >> 4;   // -> broadcast e reads within warp half
    const int m0 = mg * 8;

    float best_s[8];
    int   best_k[8];
    #pragma unroll
    for (int i = 0; i < 8; i++) { best_s[i] = -3.0e38f; best_k[i] = 0; }

    #pragma unroll
    for (int kc = 0; kc < 2; kc++) {
        const int k0 = kg * 32 + kc * 16;
        unsigned long long acc[8][8];   // [m][k-pair], f32x2 accumulators
        #pragma unroll
        for (int i = 0; i < 8; i++)
            #pragma unroll
            for (int j = 0; j < 8; j++) acc[i][j] = 0ull;

        const float* sxp = sx + m0;
        const float* sep = se + k0;

        #pragma unroll 4
        for (int d = 0; d < D; d++) {
            float4 xa = *(const float4*)(sxp + d * MT);
            float4 xb = *(const float4*)(sxp + d * MT + 4);
            ulonglong2 ea = *(const ulonglong2*)(sep + d * K);
            ulonglong2 eb = *(const ulonglong2*)(sep + d * K + 4);
            ulonglong2 ec = *(const ulonglong2*)(sep + d * K + 8);
            ulonglong2 ed = *(const ulonglong2*)(sep + d * K + 12);
            unsigned long long e2[8] = {ea.x, ea.y, eb.x, eb.y, ec.x, ec.y, ed.x, ed.y};

            unsigned xv[8] = {__float_as_uint(xa.x), __float_as_uint(xa.y),
                              __float_as_uint(xa.z), __float_as_uint(xa.w),
                              __float_as_uint(xb.x), __float_as_uint(xb.y),
                              __float_as_uint(xb.z), __float_as_uint(xb.w)};
            unsigned long long xd[8];
            #pragma unroll
            for (int i = 0; i < 8; i++)
                asm("mov.b64 %0, {%1, %1};" : "=l"(xd[i]) : "r"(xv[i]));

            #pragma unroll
            for (int i = 0; i < 8; i++)
                #pragma unroll
                for (int j = 0; j < 8; j++)
                    asm("fma.rn.f32x2 %0, %1, %2, %0;"
                        : "+l"(acc[i][j]) : "l"(e2[j]), "l"(xd[i]));
        }

        // finalize chunk: score = dot - 0.5||e||^2, keep running argmax
        #pragma unroll
        for (int i = 0; i < 8; i++) {
            #pragma unroll
            for (int j = 0; j < 8; j++) {
                float lo = __uint_as_float((unsigned)(acc[i][j] & 0xffffffffull));
                float hi = __uint_as_float((unsigned)(acc[i][j] >> 32));
                int ka = k0 + 2 * j;
                float sa = lo - shes[ka];
                float sb = hi - shes[ka + 1];
                if (sa > best_s[i]) { best_s[i] = sa; best_k[i] = ka; }
                if (sb > best_s[i]) { best_s[i] = sb; best_k[i] = ka + 1; }
            }
        }
    }

    // cross-thread argmax: pack (ordered-float score || K-1-idx) -> atomicMax.
    // Equal scores resolve to the SMALLEST index (matches jnp.argmin tiebreak).
    #pragma unroll
    for (int i = 0; i < 8; i++) {
        unsigned u = __float_as_uint(best_s[i]);
        u = (u & 0x80000000u) ? ~u : (u | 0x80000000u);
        unsigned long long key =
            ((unsigned long long)u << 32) | (unsigned)(K - 1 - best_k[i]);
        atomicMax(&sbest[m0 + i], key);
    }
    __syncthreads();

    // Emit quantized vectors (NHWC: pixel-major, 64 contiguous floats each)
    for (int i = tid; i < MT * (D / 4); i += T) {
        int j = i >> 4, c4 = i & 15;
        int idx = (K - 1) - (int)(sbest[j] & 0xffffffffull);
        float4 v = *(const float4*)(embed + idx * D + (c4 << 2));
        *(float4*)(outq + ((size_t)(n0 + j)) * D + (c4 << 2)) = v;
    }
    // Emit indices (second output region), as float
    if (outi) {
        for (int i = tid; i < MT; i += T) {
            int idx = (K - 1) - (int)(sbest[i] & 0xffffffffull);
            outi[n0 + i] = (float)idx;
        }
    }
}

// ---------------------------------------------------------------------------
extern "C" void kernel_launch(void* const* d_in, const int* in_sizes, int n_in,
                              void* d_out, int out_size) {
    const float* x     = (const float*)d_in[0];
    const float* embed = (const float*)d_in[1];
    float* out = (float*)d_out;

    const int N = in_sizes[0] / D;   // 131072 pixels
    float* outi = nullptr;
    if (out_size >= N * D + N) outi = out + (size_t)N * D;

    size_t smem_bytes = (size_t)(D * K + D * MT + K) * sizeof(float)
                      + (size_t)MT * sizeof(unsigned long long);
    cudaFuncSetAttribute(vq_main, cudaFuncAttributeMaxDynamicSharedMemorySize,
                         (int)smem_bytes);

    vq_prep<<<K, D>>>(embed);
    vq_main<<<N / MT, T, smem_bytes>>>(x, embed, out, outi);
}